// round 1
// baseline (speedup 1.0000x reference)
#include <cuda_runtime.h>
#include <math.h>

#define DD 64
#define NMAX 50000
#define EMAX 800000
#define INV_SQRT2 0.70710678118654752440f

// ---- scratch (device globals: allocation-free) ----
__device__ float g_emb[(size_t)EMAX * DD];   // bond-encoder output, computed once
__device__ float g_agg[(size_t)NMAX * DD];   // per-layer scatter-add target
__device__ float g_h[(size_t)NMAX * DD];     // MLP output (pre-BN)
__device__ float g_xa[(size_t)NMAX * DD];    // x ping
__device__ float g_xb[(size_t)NMAX * DD];    // x pong
__device__ float g_bsum[DD];                 // BN sum per feature
__device__ float g_bsq[DD];                  // BN sumsq per feature

__device__ __forceinline__ float gelu_exact(float v) {
    // matches jax.nn.gelu(approximate=False): v * Phi(v)
    return v * normcdff(v);
}

// device-side x-buffer selection (avoids host symbol-address lookups during capture)
__device__ __forceinline__ const float* sel_in(int s, const float* ext) {
    return (s == 0) ? ext : ((s == 1) ? g_xa : g_xb);
}
__device__ __forceinline__ float* sel_out(int s, float* ext) {
    return (s == 0) ? ext : ((s == 1) ? g_xa : g_xb);
}

// ============================================================
// K0: edge_emb = edge_attr @ W_be + b_be   (done once)
// 2 warps per edge row; each thread owns one output dim (W column in 64 regs).
// attr row read as warp-uniform float4 LDG (L1 broadcast).
// ============================================================
__global__ void k_bond(const float* __restrict__ attr,
                       const float* __restrict__ Wbe,
                       const float* __restrict__ bbe, int E)
{
    int gw   = (blockIdx.x * blockDim.x + threadIdx.x) >> 5;
    int lane = threadIdx.x & 31;
    int nw   = (gridDim.x * blockDim.x) >> 5;
    int half = gw & 1;
    int d    = half * 32 + lane;

    float w[DD];
#pragma unroll
    for (int k = 0; k < DD; k++) w[k] = Wbe[k * DD + d];
    float bias = bbe[d];

    for (int row = (gw >> 1); row < E; row += (nw >> 1)) {
        const float4* a4 = (const float4*)(attr + (size_t)row * DD);
        float acc = bias;
#pragma unroll
        for (int k4 = 0; k4 < 16; k4++) {
            float4 a = a4[k4];
            acc = fmaf(a.x, w[4 * k4 + 0], acc);
            acc = fmaf(a.y, w[4 * k4 + 1], acc);
            acc = fmaf(a.z, w[4 * k4 + 2], acc);
            acc = fmaf(a.w, w[4 * k4 + 3], acc);
        }
        g_emb[(size_t)row * DD + d] = acc;
    }
}

// ============================================================
// K1: zero agg + BN stats
// ============================================================
__global__ void k_zero(int N)
{
    int idx = blockIdx.x * blockDim.x + threadIdx.x;
    int tot = N * 16;
    if (idx < tot) ((float4*)g_agg)[idx] = make_float4(0.f, 0.f, 0.f, 0.f);
    if (idx < DD) { g_bsum[idx] = 0.f; g_bsq[idx] = 0.f; }
}

// ============================================================
// K2: m = gelu(x[src] + emb); agg[dst] += m   (vector RED, 16B)
// one thread per (edge, 4-dim group)
// ============================================================
__global__ void k_msg(int xsel, const float* __restrict__ xext,
                      const int* __restrict__ src,
                      const int* __restrict__ dst, int E)
{
    int idx = blockIdx.x * blockDim.x + threadIdx.x;
    int tot = E * 16;
    if (idx >= tot) return;
    const float* x = sel_in(xsel, xext);
    int e = idx >> 4, q = idx & 15;
    int s = src[e], t = dst[e];
    float4 v  = ((const float4*)g_emb)[(size_t)e * 16 + q];
    float4 xs = ((const float4*)x)[(size_t)s * 16 + q];
    v.x = gelu_exact(v.x + xs.x);
    v.y = gelu_exact(v.y + xs.y);
    v.z = gelu_exact(v.z + xs.z);
    v.w = gelu_exact(v.w + xs.w);
    float4* p = ((float4*)g_agg) + (size_t)t * 16 + q;
#if defined(__CUDA_ARCH__) && (__CUDA_ARCH__ >= 900)
    atomicAdd(p, v);                      // HW 16B vector reduction (sm_90+)
#else
    float* pf = (float*)p;
    atomicAdd(pf + 0, v.x);
    atomicAdd(pf + 1, v.y);
    atomicAdd(pf + 2, v.z);
    atomicAdd(pf + 3, v.w);
#endif
}

// ============================================================
// K3: h = gelu(((1+eps)x + agg) @ W1 + b1) @ W2 + b2 ; accumulate BN stats
// 64 threads/block, thread d holds W1/W2 column in registers, rows via smem.
// ============================================================
__global__ void __launch_bounds__(64) k_mlp(
    int xsel, const float* __restrict__ xext,
    const float* __restrict__ W1, const float* __restrict__ b1,
    const float* __restrict__ W2, const float* __restrict__ b2,
    const float* __restrict__ epsp, int layer, int N)
{
    __shared__ float4 s_in4[16];
    __shared__ float4 s_h14[16];
    float* s_in = (float*)s_in4;
    float* s_h1 = (float*)s_h14;

    const float* x = sel_in(xsel, xext);
    int d = threadIdx.x;

    float w1[DD], w2[DD];
#pragma unroll
    for (int k = 0; k < DD; k++) w1[k] = W1[k * DD + d];
#pragma unroll
    for (int k = 0; k < DD; k++) w2[k] = W2[k * DD + d];
    float bb1 = b1[d], bb2 = b2[d];
    float eps1 = 1.0f + epsp[layer];

    float lsum = 0.f, lsq = 0.f;

    for (int row = blockIdx.x; row < N; row += gridDim.x) {
        s_in[d] = fmaf(eps1, x[(size_t)row * DD + d], g_agg[(size_t)row * DD + d]);
        __syncthreads();

        float acc = bb1;
#pragma unroll
        for (int k4 = 0; k4 < 16; k4++) {
            float4 a = s_in4[k4];
            acc = fmaf(a.x, w1[4 * k4 + 0], acc);
            acc = fmaf(a.y, w1[4 * k4 + 1], acc);
            acc = fmaf(a.z, w1[4 * k4 + 2], acc);
            acc = fmaf(a.w, w1[4 * k4 + 3], acc);
        }
        s_h1[d] = gelu_exact(acc);
        __syncthreads();

        float acc2 = bb2;
#pragma unroll
        for (int k4 = 0; k4 < 16; k4++) {
            float4 a = s_h14[k4];
            acc2 = fmaf(a.x, w2[4 * k4 + 0], acc2);
            acc2 = fmaf(a.y, w2[4 * k4 + 1], acc2);
            acc2 = fmaf(a.z, w2[4 * k4 + 2], acc2);
            acc2 = fmaf(a.w, w2[4 * k4 + 3], acc2);
        }
        g_h[(size_t)row * DD + d] = acc2;
        lsum += acc2;
        lsq  = fmaf(acc2, acc2, lsq);
        // no third sync needed: next s_in write is ordered by the two barriers above
    }
    atomicAdd(&g_bsum[d], lsum);
    atomicAdd(&g_bsq[d],  lsq);
}

// ============================================================
// K4: x_next = (x + gelu(BN(h))) * INV_SQRT2
// ============================================================
__global__ void k_bn(int xsel, const float* __restrict__ xext,
                     int osel, float* __restrict__ oext,
                     const float* __restrict__ gamma,
                     const float* __restrict__ beta, int N)
{
    int idx = blockIdx.x * blockDim.x + threadIdx.x;
    int tot = N * 16;
    if (idx >= tot) return;
    const float* xin = sel_in(xsel, xext);
    float* xout = sel_out(osel, oext);

    int q = idx & 15;
    float invN = 1.0f / (float)N;
    float4 hv = ((const float4*)g_h)[idx];
    float4 xv = ((const float4*)xin)[idx];
    float hvv[4] = {hv.x, hv.y, hv.z, hv.w};
    float xvv[4] = {xv.x, xv.y, xv.z, xv.w};
    float o[4];
#pragma unroll
    for (int j = 0; j < 4; j++) {
        int dd = q * 4 + j;
        float mu   = g_bsum[dd] * invN;
        float var  = g_bsq[dd] * invN - mu * mu;
        float rstd = rsqrtf(var + 1e-5f);
        float hn   = (hvv[j] - mu) * rstd * gamma[dd] + beta[dd];
        o[j] = (xvv[j] + gelu_exact(hn)) * INV_SQRT2;
    }
    ((float4*)xout)[idx] = make_float4(o[0], o[1], o[2], o[3]);
}

// ============================================================
// launcher
// ============================================================
extern "C" void kernel_launch(void* const* d_in, const int* in_sizes, int n_in,
                              void* d_out, int out_size)
{
    const float* x0    = (const float*)d_in[0];
    const int*   eidx  = (const int*)  d_in[1];
    const float* eattr = (const float*)d_in[2];
    const float* Wbe   = (const float*)d_in[3];
    const float* bbe   = (const float*)d_in[4];
    const float* epsp  = (const float*)d_in[5];
    const float* W1    = (const float*)d_in[6];
    const float* b1    = (const float*)d_in[7];
    const float* W2    = (const float*)d_in[8];
    const float* b2    = (const float*)d_in[9];
    const float* gamma = (const float*)d_in[10];
    const float* beta  = (const float*)d_in[11];

    int N = in_sizes[0] / DD;
    int E = in_sizes[1] / 2;
    const int* src = eidx;
    const int* dst = eidx + E;

    // bond encoder once (shared across layers)
    k_bond<<<592, 256>>>(eattr, Wbe, bbe, E);

    // x buffer schedule: layer0: in=ext(x0) -> g_xa ; layer1: g_xa -> g_xb ; layer2: g_xb -> ext(d_out)
    int  in_sel[3]  = {0, 1, 2};
    int  out_sel[3] = {1, 2, 0};

    int nblk_node = (N * 16 + 255) / 256;
    int nblk_edge = (E * 16 + 255) / 256;

    for (int l = 0; l < 3; l++) {
        const float* xext = (l == 0) ? x0 : nullptr;
        k_zero<<<nblk_node, 256>>>(N);
        k_msg <<<nblk_edge, 256>>>(in_sel[l], xext, src, dst, E);
        k_mlp <<<2048, 64>>>(in_sel[l], xext,
                             W1 + (size_t)l * DD * DD, b1 + (size_t)l * DD,
                             W2 + (size_t)l * DD * DD, b2 + (size_t)l * DD,
                             epsp, l, N);
        k_bn  <<<nblk_node, 256>>>(in_sel[l], xext, out_sel[l], (float*)d_out,
                                   gamma + (size_t)l * DD, beta + (size_t)l * DD, N);
    }
}